// round 13
// baseline (speedup 1.0000x reference)
#include <cuda_runtime.h>
#include <cuda_bf16.h>
#include <math.h>
#include <stdint.h>

#define B_  4
#define L_  2048
#define D_  2048
#define H_  16
#define HD  128
#define BH  (B_*H_)

// ---------------- device scratch (allocation-free rule: __device__ globals) ----
__device__ float g_q[(size_t)BH * L_ * HD];     // (B,H,L,d)
__device__ float g_k[(size_t)BH * L_ * HD];     // (B,H,L,d)
__device__ float g_v[(size_t)BH * L_ * HD];     // (B,H,L,d)
__device__ float g_att[(size_t)B_ * L_ * D_];   // (B,L,H,d)
__device__ float g_qsq[BH * L_];
__device__ float g_ksq[BH * L_];
__device__ float g_cos[L_ * 64];
__device__ float g_sin[L_ * 64];

// ---------------- mma helpers ----------------------------------------------------
__device__ __forceinline__ uint32_t f2tf32(float x) {
    uint32_t r;
    asm("cvt.rna.tf32.f32 %0, %1;" : "=r"(r) : "f"(x));
    return r;
}
__device__ __forceinline__ void mma_tf32(float (&d)[4], const uint32_t (&a)[4],
                                         uint32_t b0, uint32_t b1) {
    asm volatile(
        "mma.sync.aligned.m16n8k8.row.col.f32.tf32.tf32.f32 "
        "{%0,%1,%2,%3}, {%4,%5,%6,%7}, {%8,%9}, {%0,%1,%2,%3};"
        : "+f"(d[0]), "+f"(d[1]), "+f"(d[2]), "+f"(d[3])
        : "r"(a[0]), "r"(a[1]), "r"(a[2]), "r"(a[3]), "r"(b0), "r"(b1));
}
__device__ __forceinline__ void mma_bf16(float (&d)[4], const uint32_t (&a)[4],
                                         uint32_t b0, uint32_t b1) {
    asm volatile(
        "mma.sync.aligned.m16n8k16.row.col.f32.bf16.bf16.f32 "
        "{%0,%1,%2,%3}, {%4,%5,%6,%7}, {%8,%9}, {%0,%1,%2,%3};"
        : "+f"(d[0]), "+f"(d[1]), "+f"(d[2]), "+f"(d[3])
        : "r"(a[0]), "r"(a[1]), "r"(a[2]), "r"(a[3]), "r"(b0), "r"(b1));
}
__device__ __forceinline__ uint32_t bfpack(float lo, float hi) {
    uint32_t d;
    asm("cvt.rn.bf16x2.f32 %0, %1, %2;" : "=r"(d) : "f"(hi), "f"(lo));
    return d;
}
__device__ __forceinline__ float bfhi(float f) {
    return __bfloat162float(__float2bfloat16(f));
}

// ---------------- RoPE tables (double-precision truth) ------------------------
__global__ void rope_table_kernel() {
    int l = blockIdx.x;
    int i = threadIdx.x;                       // 0..63
    double invf = exp(((double)(-2 * i) / 128.0) * log(10000.0));
    double th = (double)l * invf;
    double s, c;
    sincos(th, &s, &c);
    g_cos[l * 64 + i] = (float)c;
    g_sin[l * 64 + i] = (float)s;
}

// ---------------- GEMM core: distance-2 prefetch + paired LDS.64 ----------------
// 128x128 CTA tile, 256 threads, 8 warps 4x2, warp tile m32 x n64.
// Smem rows hold 16 tf32 words as 8 (k, k+4) pairs: word p = (ks*4 + (k&3))*2
// + ((k>>2)&1), row stride 20 (2-way LDS.64 conflicts). Double-buffered smem;
// LDG issued TWO iterations ahead via two register staging sets.
#define BM 128
#define BN 128
#define BK 16
#define RSTR 20   // words per smem row (16 + 4 pad)

__device__ __forceinline__ void gm_stage(uint32_t* __restrict__ Ab,
                                         uint32_t* __restrict__ Wb,
                                         const float4 (&va)[2], const float4 (&vw)[2],
                                         int ldr, int ldc) {
    const int base = (ldc >> 3) * 8 + ((ldc >> 2) & 1);   // ks8 + half
#pragma unroll
    for (int p = 0; p < 2; p++) {
        const int r = ldr + p * 64;
        uint32_t* a = Ab + r * RSTR + base;
        a[0] = f2tf32(va[p].x); a[2] = f2tf32(va[p].y);
        a[4] = f2tf32(va[p].z); a[6] = f2tf32(va[p].w);
        uint32_t* w = Wb + r * RSTR + base;
        w[0] = f2tf32(vw[p].x); w[2] = f2tf32(vw[p].y);
        w[4] = f2tf32(vw[p].z); w[6] = f2tf32(vw[p].w);
    }
}

__device__ __forceinline__ void gm_load(const float* __restrict__ A,
                                        const float* __restrict__ W,
                                        int K, int bm, int bn, int k0,
                                        int ldr, int ldc,
                                        float4 (&va)[2], float4 (&vw)[2]) {
#pragma unroll
    for (int p = 0; p < 2; p++) {
        const int r = ldr + p * 64;
        va[p] = *(const float4*)(A + (size_t)(bm + r) * K + k0 + ldc);
        vw[p] = *(const float4*)(W + (size_t)(bn + r) * K + k0 + ldc);
    }
}

__device__ __forceinline__ void sgemm_compute_mma(const float* __restrict__ A,
                                                  const float* __restrict__ W,
                                                  int K, int bm, int bn,
                                                  float (&acc)[2][8][4]) {
    __shared__ uint32_t As[2][128 * RSTR];
    __shared__ uint32_t Ws[2][128 * RSTR];
    const int tid  = threadIdx.x;
    const int warp = tid >> 5, lane = tid & 31;
    const int wm0 = (warp >> 1) * 32, wn0 = (warp & 1) * 64;
    const int lr = lane >> 2;
    const int lc = lane & 3;
    const int ldr = tid >> 2;              // 0..63
    const int ldc = (tid & 3) << 2;        // 0,4,8,12

#pragma unroll
    for (int mt = 0; mt < 2; mt++)
#pragma unroll
        for (int nt = 0; nt < 8; nt++)
#pragma unroll
            for (int i = 0; i < 4; i++) acc[mt][nt][i] = 0.f;

    const int nit = K / BK;
    float4 va[2][2], vw[2][2];             // two staging sets

    // prologue: it0 -> set0 -> buf0; it1 -> set1
    gm_load(A, W, K, bm, bn, 0, ldr, ldc, va[0], vw[0]);
    gm_stage(As[0], Ws[0], va[0], vw[0], ldr, ldc);
    if (nit > 1) gm_load(A, W, K, bm, bn, BK, ldr, ldc, va[1], vw[1]);
    __syncthreads();

    for (int it = 0; it < nit; it++) {
        const int cur = it & 1;

        // issue LDG for tile it+2 into the set freed last iteration
        if (it + 2 < nit)
            gm_load(A, W, K, bm, bn, (it + 2) * BK, ldr, ldc,
                    va[cur], vw[cur]);

        // compute on current buffer (paired LDS.64 fragments)
        const uint32_t* Ab = As[cur];
        const uint32_t* Wb = Ws[cur];
#pragma unroll
        for (int ks = 0; ks < 2; ks++) {
            const int pa = ks * 8 + lc * 2;
            uint32_t a[2][4];
#pragma unroll
            for (int mt = 0; mt < 2; mt++) {
                const int r = wm0 + mt * 16 + lr;
                uint2 u0 = *(const uint2*)(Ab + r * RSTR + pa);
                uint2 u1 = *(const uint2*)(Ab + (r + 8) * RSTR + pa);
                a[mt][0] = u0.x; a[mt][1] = u1.x;
                a[mt][2] = u0.y; a[mt][3] = u1.y;
            }
#pragma unroll
            for (int nt = 0; nt < 8; nt++) {
                const int n = wn0 + nt * 8 + lr;
                uint2 ub = *(const uint2*)(Wb + n * RSTR + pa);
                mma_tf32(acc[0][nt], a[0], ub.x, ub.y);
                mma_tf32(acc[1][nt], a[1], ub.x, ub.y);
            }
        }

        // stage tile it+1 (loaded two iterations ago) into the other buffer
        if (it + 1 < nit) {
            const int nxt = 1 - cur;
            gm_stage(As[nxt], Ws[nxt], va[nxt], vw[nxt], ldr, ldc);
        }
        __syncthreads();
    }
}

__global__ void __launch_bounds__(256, 2) sgemm_qkv_kernel(const float* __restrict__ x,
                                                           const float* __restrict__ Wq,
                                                           const float* __restrict__ Wk,
                                                           const float* __restrict__ Wv) {
    const int z = blockIdx.z;
    const float* W = (z == 0) ? Wq : (z == 1) ? Wk : Wv;
    float* dst = (z == 0) ? g_q : (z == 1) ? g_k : g_v;
    float acc[2][8][4];
    const int bm = blockIdx.y * BM, bn = blockIdx.x * BN;
    sgemm_compute_mma(x, W, D_, bm, bn, acc);

    const int warp = threadIdx.x >> 5, lane = threadIdx.x & 31;
    const int wm0 = (warp >> 1) * 32, wn0 = (warp & 1) * 64;
    const int lr = lane >> 2, lc = lane & 3;
    const int h = bn >> 7;
#pragma unroll
    for (int mt = 0; mt < 2; mt++) {
        const int mlo = bm + wm0 + mt * 16 + lr;
#pragma unroll
        for (int nt = 0; nt < 8; nt++) {
            const int jj = wn0 + nt * 8 + 2 * lc;
#pragma unroll
            for (int half = 0; half < 2; half++) {
                const int m = mlo + half * 8;
                const int bb = m >> 11, l = m & 2047;
                float* p = dst + (((size_t)(bb * H_ + h) * L_ + l) * HD + jj);
                *(float2*)p = make_float2(acc[mt][nt][half * 2],
                                          acc[mt][nt][half * 2 + 1]);
            }
        }
    }
}

__global__ void __launch_bounds__(256, 2) sgemm_out_kernel(const float* __restrict__ Wo,
                                                           float* __restrict__ C) {
    float acc[2][8][4];
    const int bm = blockIdx.y * BM, bn = blockIdx.x * BN;
    sgemm_compute_mma(g_att, Wo, D_, bm, bn, acc);

    const int warp = threadIdx.x >> 5, lane = threadIdx.x & 31;
    const int wm0 = (warp >> 1) * 32, wn0 = (warp & 1) * 64;
    const int lr = lane >> 2, lc = lane & 3;
#pragma unroll
    for (int mt = 0; mt < 2; mt++) {
        const int mlo = bm + wm0 + mt * 16 + lr;
#pragma unroll
        for (int nt = 0; nt < 8; nt++) {
            const int n0 = bn + wn0 + nt * 8 + 2 * lc;
#pragma unroll
            for (int half = 0; half < 2; half++) {
                const size_t m = mlo + half * 8;
                *(float2*)(C + m * D_ + n0) = make_float2(acc[mt][nt][half * 2],
                                                          acc[mt][nt][half * 2 + 1]);
            }
        }
    }
}

// ---------------- RoPE + sigmoid + row sum-of-squares --------------------------
__global__ void rope_kernel() {
    const int l = blockIdx.x, bh = blockIdx.y, j = threadIdx.x;
    const size_t base = ((size_t)bh * L_ + l) * HD;
    const float c = g_cos[l * 64 + (j & 63)];
    const float s = g_sin[l * 64 + (j & 63)];

    __shared__ float qr[128], kr[128];
    float qv = g_q[base + j], kv = g_k[base + j];
    qr[j] = qv; kr[j] = kv;
    __syncthreads();
    float qpart = (j < 64) ? -qr[j + 64] : qr[j - 64];
    float kpart = (j < 64) ? -kr[j + 64] : kr[j - 64];
    float qo = qv * c + qpart * s;
    float ko = kv * c + kpart * s;
    float qt = 1.f / (1.f + expf(-qo));
    float kt = 1.f / (1.f + expf(-ko));
    g_q[base + j] = qt;
    g_k[base + j] = kt;

    float q2 = qt * qt, k2 = kt * kt;
#pragma unroll
    for (int o = 16; o; o >>= 1) {
        q2 += __shfl_xor_sync(0xffffffffu, q2, o);
        k2 += __shfl_xor_sync(0xffffffffu, k2, o);
    }
    __shared__ float rq[4], rk[4];
    if ((j & 31) == 0) { rq[j >> 5] = q2; rk[j >> 5] = k2; }
    __syncthreads();
    if (j == 0) g_qsq[(size_t)bh * L_ + l] = rq[0] + rq[1] + rq[2] + rq[3];
    if (j == 1) g_ksq[(size_t)bh * L_ + l] = rk[0] + rk[1] + rk[2] + rk[3];
}

// ---------------- causal flash attention (EXACT R12 — proven 963us) --------------
#define QPW 68
#define KPW 68
#define VPW 264
#define FP_STR 68
#define OFF_QH 0
#define OFF_QL (128*QPW)
#define OFF_KH (2*128*QPW)
#define OFF_KL (OFF_KH + 64*KPW)
#define OFF_VP (OFF_KL + 64*KPW)
#define OFF_PS (OFF_VP + 32*VPW)
#define OFF_SQS (OFF_PS + 128*FP_STR)
#define OFF_SKS (OFF_SQS + 128)
#define FLASH_SMEM ((OFF_SKS + 64) * 4)

__global__ void __launch_bounds__(256) flash_kernel(const float* __restrict__ tau_p) {
    extern __shared__ uint32_t smu[];
    float* sqs = (float*)(smu + OFF_SQS);
    float* sks = (float*)(smu + OFF_SKS);
    uint32_t* Pu = smu + OFF_PS;

    const int qi = blockIdx.x;
    const int bh = blockIdx.y;
    const int b = bh >> 4, h = bh & 15;
    const int tid = threadIdx.x;
    const int lane = tid & 31, warp = tid >> 5;
    const int lr = lane >> 2, lc = lane & 3;
    const int r0 = warp * 16 + lr;

    float tr = tau_p[0];
    float tau = log1pf(expf(tr));
    tau = fminf(fmaxf(tau, 0.1f), 10.f);
    const float inv_tau = 1.f / tau;

    const size_t hbase = (size_t)bh * L_ * HD;
    const float* Qg = g_q + hbase + (size_t)qi * 128 * HD;

#pragma unroll
    for (int t = 0; t < 16; t++) {
        int idx = tid + t * 256;
        int row = idx >> 5, c4 = idx & 31;
        float4 v = *(const float4*)(Qg + (size_t)row * HD + c4 * 4);
        float hx = bfhi(v.x), hy = bfhi(v.y), hz = bfhi(v.z), hw = bfhi(v.w);
        int kpa = 2 * c4, kpb = kpa + 1;
        int sa = kpa >> 3, ja = kpa & 7;
        int ia = row * QPW + ((sa << 2) + (ja & 3)) * 2 + (ja >> 2);
        int sb = kpb >> 3, jb = kpb & 7;
        int ib = row * QPW + ((sb << 2) + (jb & 3)) * 2 + (jb >> 2);
        smu[OFF_QH + ia] = bfpack(hx, hy);
        smu[OFF_QL + ia] = bfpack(v.x - hx, v.y - hy);
        smu[OFF_QH + ib] = bfpack(hz, hw);
        smu[OFF_QL + ib] = bfpack(v.z - hz, v.w - hw);
    }
    if (tid < 128) sqs[tid] = g_qsq[(size_t)bh * L_ + qi * 128 + tid];

    float m_i[2] = {-INFINITY, -INFINITY};
    float l_i[2] = {0.f, 0.f};
    float O[16][4];
#pragma unroll
    for (int nf = 0; nf < 16; nf++)
#pragma unroll
        for (int i = 0; i < 4; i++) O[nf][i] = 0.f;

    const int ntk = 2 * qi + 2;
    for (int kt = 0; kt < ntk; kt++) {
        const int j0 = kt * 64;
        __syncthreads();

#pragma unroll
        for (int t = 0; t < 8; t++) {
            int idx = tid + t * 256;
            int row = idx >> 5, c4 = idx & 31;
            float4 v = *(const float4*)(g_k + hbase + (size_t)(j0 + row) * HD + c4 * 4);
            float hx = bfhi(v.x), hy = bfhi(v.y), hz = bfhi(v.z), hw = bfhi(v.w);
            int kpa = 2 * c4, kpb = kpa + 1;
            int sa = kpa >> 3, ja = kpa & 7;
            int ia = row * KPW + ((sa << 2) + (ja & 3)) * 2 + (ja >> 2);
            int sb = kpb >> 3, jb = kpb & 7;
            int ib = row * KPW + ((sb << 2) + (jb & 3)) * 2 + (jb >> 2);
            smu[OFF_KH + ia] = bfpack(hx, hy);
            smu[OFF_KL + ia] = bfpack(v.x - hx, v.y - hy);
            smu[OFF_KH + ib] = bfpack(hz, hw);
            smu[OFF_KL + ib] = bfpack(v.z - hz, v.w - hw);
        }
#pragma unroll
        for (int t = 0; t < 8; t++) {
            int idx = tid + t * 256;
            int k = idx >> 5, c4 = idx & 31;
            float4 v = *(const float4*)(g_v + hbase + (size_t)(j0 + k) * HD + c4 * 4);
            int ks = k >> 3, j = k & 7;
            int pr = (ks << 2) + (j & 3), half = j >> 2;
            uint32_t base = OFF_VP + pr * VPW + (c4 * 4) * 2 + half;
            smu[base + 0] = f2tf32(v.x);
            smu[base + 2] = f2tf32(v.y);
            smu[base + 4] = f2tf32(v.z);
            smu[base + 6] = f2tf32(v.w);
        }
        if (tid < 64) sks[tid] = g_ksq[(size_t)bh * L_ + j0 + tid];
        __syncthreads();

        float sacc[8][4];
#pragma unroll
        for (int nf = 0; nf < 8; nf++)
#pragma unroll
            for (int i = 0; i < 4; i++) sacc[nf][i] = 0.f;

#pragma unroll
        for (int s8 = 0; s8 < 8; s8++) {
            const int ci = ((s8 << 2) + lc) * 2;
            uint2 qh0 = *(const uint2*)(smu + OFF_QH + r0 * QPW + ci);
            uint2 qh1 = *(const uint2*)(smu + OFF_QH + (r0 + 8) * QPW + ci);
            uint2 ql0 = *(const uint2*)(smu + OFF_QL + r0 * QPW + ci);
            uint2 ql1 = *(const uint2*)(smu + OFF_QL + (r0 + 8) * QPW + ci);
            uint32_t ah[4] = {qh0.x, qh1.x, qh0.y, qh1.y};
            uint32_t al[4] = {ql0.x, ql1.x, ql0.y, ql1.y};
#pragma unroll
            for (int nf = 0; nf < 8; nf++) {
                const int n = nf * 8 + lr;
                uint2 bhp = *(const uint2*)(smu + OFF_KH + n * KPW + ci);
                uint2 blp = *(const uint2*)(smu + OFF_KL + n * KPW + ci);
                mma_bf16(sacc[nf], ah, bhp.x, bhp.y);
                mma_bf16(sacc[nf], ah, blp.x, blp.y);
                mma_bf16(sacc[nf], al, bhp.x, bhp.y);
            }
        }

        const float sq0 = sqs[r0], sq1 = sqs[r0 + 8];
        const int gq0 = qi * 128 + r0, gq1 = gq0 + 8;
        float rm[2] = {-INFINITY, -INFINITY};
#pragma unroll
        for (int nf = 0; nf < 8; nf++) {
            const int cb = j0 + nf * 8 + 2 * lc;
            const float kq0 = sks[nf * 8 + 2 * lc];
            const float kq1 = sks[nf * 8 + 2 * lc + 1];
            float v00 = (2.f * sacc[nf][0] - sq0 - kq0) * inv_tau;
            float v01 = (2.f * sacc[nf][1] - sq0 - kq1) * inv_tau;
            float v10 = (2.f * sacc[nf][2] - sq1 - kq0) * inv_tau;
            float v11 = (2.f * sacc[nf][3] - sq1 - kq1) * inv_tau;
            v00 = (cb > gq0) ? -INFINITY : v00;
            v01 = (cb + 1 > gq0) ? -INFINITY : v01;
            v10 = (cb > gq1) ? -INFINITY : v10;
            v11 = (cb + 1 > gq1) ? -INFINITY : v11;
            sacc[nf][0] = v00; sacc[nf][1] = v01;
            sacc[nf][2] = v10; sacc[nf][3] = v11;
            rm[0] = fmaxf(rm[0], fmaxf(v00, v01));
            rm[1] = fmaxf(rm[1], fmaxf(v10, v11));
        }
#pragma unroll
        for (int i = 0; i < 2; i++) {
            rm[i] = fmaxf(rm[i], __shfl_xor_sync(0xffffffffu, rm[i], 1));
            rm[i] = fmaxf(rm[i], __shfl_xor_sync(0xffffffffu, rm[i], 2));
        }
        float mnew[2], scale[2], rs[2] = {0.f, 0.f};
#pragma unroll
        for (int i = 0; i < 2; i++) {
            mnew[i] = fmaxf(m_i[i], rm[i]);
            scale[i] = __expf(m_i[i] - mnew[i]);
        }
#pragma unroll
        for (int nf = 0; nf < 8; nf++) {
            float p00 = __expf(sacc[nf][0] - mnew[0]);
            float p01 = __expf(sacc[nf][1] - mnew[0]);
            float p10 = __expf(sacc[nf][2] - mnew[1]);
            float p11 = __expf(sacc[nf][3] - mnew[1]);
            rs[0] += p00 + p01;
            rs[1] += p10 + p11;
            const int cc = nf * 8 + 2 * lc;
            *(uint2*)(Pu + r0 * FP_STR + cc) = make_uint2(f2tf32(p00), f2tf32(p01));
            *(uint2*)(Pu + (r0 + 8) * FP_STR + cc) = make_uint2(f2tf32(p10), f2tf32(p11));
        }
#pragma unroll
        for (int i = 0; i < 2; i++) {
            rs[i] += __shfl_xor_sync(0xffffffffu, rs[i], 1);
            rs[i] += __shfl_xor_sync(0xffffffffu, rs[i], 2);
            l_i[i] = l_i[i] * scale[i] + rs[i];
            m_i[i] = mnew[i];
        }
#pragma unroll
        for (int nf = 0; nf < 16; nf++) {
            O[nf][0] *= scale[0]; O[nf][1] *= scale[0];
            O[nf][2] *= scale[1]; O[nf][3] *= scale[1];
        }
        __syncwarp();

#pragma unroll
        for (int ks = 0; ks < 8; ks++) {
            const int kb = ks * 8;
            uint32_t pa[4];
            pa[0] = Pu[r0 * FP_STR + kb + lc];
            pa[1] = Pu[(r0 + 8) * FP_STR + kb + lc];
            pa[2] = Pu[r0 * FP_STR + kb + lc + 4];
            pa[3] = Pu[(r0 + 8) * FP_STR + kb + lc + 4];
            const uint32_t vbase = OFF_VP + ((ks << 2) + lc) * VPW;
#pragma unroll
            for (int nf = 0; nf < 16; nf++) {
                const int n = nf * 8 + lr;
                uint2 bv = *(const uint2*)(smu + vbase + 2 * n);
                mma_tf32(O[nf], pa, bv.x, bv.y);
            }
        }
    }

    const float il0 = 1.f / l_i[0], il1 = 1.f / l_i[1];
    const int gq0 = qi * 128 + r0;
#pragma unroll
    for (int nf = 0; nf < 16; nf++) {
        const int col = nf * 8 + 2 * lc;
        size_t off0 = (((size_t)b * L_ + gq0) * H_ + h) * HD + col;
        size_t off1 = (((size_t)b * L_ + gq0 + 8) * H_ + h) * HD + col;
        *(float2*)&g_att[off0] = make_float2(O[nf][0] * il0, O[nf][1] * il0);
        *(float2*)&g_att[off1] = make_float2(O[nf][2] * il1, O[nf][3] * il1);
    }
}

// ---------------- launch --------------------------------------------------------
extern "C" void kernel_launch(void* const* d_in, const int* in_sizes, int n_in,
                              void* d_out, int out_size) {
    const float* x   = (const float*)d_in[0];
    const float* Wq  = (const float*)d_in[1];
    const float* Wk  = (const float*)d_in[2];
    const float* Wv  = (const float*)d_in[3];
    const float* Wo  = (const float*)d_in[4];
    const float* tau = (const float*)d_in[5];
    float* out = (float*)d_out;

    cudaFuncSetAttribute(flash_kernel, cudaFuncAttributeMaxDynamicSharedMemorySize,
                         FLASH_SMEM);

    rope_table_kernel<<<L_, 64>>>();
    sgemm_qkv_kernel<<<dim3(D_ / BN, (B_ * L_) / BM, 3), 256>>>(x, Wq, Wk, Wv);
    rope_kernel<<<dim3(L_, BH), 128>>>();
    flash_kernel<<<dim3(L_ / 128, BH), 256, FLASH_SMEM>>>(tau);
    sgemm_out_kernel<<<dim3(D_ / BN, (B_ * L_) / BM), 256>>>(Wo, out);
}

// round 15
// speedup vs baseline: 1.2620x; 1.2620x over previous
#include <cuda_runtime.h>
#include <cuda_bf16.h>
#include <math.h>
#include <stdint.h>

#define B_  4
#define L_  2048
#define D_  2048
#define H_  16
#define HD  128
#define BH  (B_*H_)

// ---------------- device scratch (allocation-free rule: __device__ globals) ----
__device__ float g_q[(size_t)BH * L_ * HD];     // (B,H,L,d)
__device__ float g_k[(size_t)BH * L_ * HD];     // (B,H,L,d)
__device__ float g_v[(size_t)BH * L_ * HD];     // (B,H,L,d)
__device__ float g_att[(size_t)B_ * L_ * D_];   // (B,L,H,d)
__device__ float g_qsq[BH * L_];
__device__ float g_ksq[BH * L_];
__device__ float g_cos[L_ * 64];
__device__ float g_sin[L_ * 64];

// ---------------- mma helpers ----------------------------------------------------
__device__ __forceinline__ uint32_t f2tf32(float x) {
    uint32_t r;
    asm("cvt.rna.tf32.f32 %0, %1;" : "=r"(r) : "f"(x));
    return r;
}
__device__ __forceinline__ void mma_tf32(float (&d)[4], const uint32_t (&a)[4],
                                         uint32_t b0, uint32_t b1) {
    asm volatile(
        "mma.sync.aligned.m16n8k8.row.col.f32.tf32.tf32.f32 "
        "{%0,%1,%2,%3}, {%4,%5,%6,%7}, {%8,%9}, {%0,%1,%2,%3};"
        : "+f"(d[0]), "+f"(d[1]), "+f"(d[2]), "+f"(d[3])
        : "r"(a[0]), "r"(a[1]), "r"(a[2]), "r"(a[3]), "r"(b0), "r"(b1));
}
__device__ __forceinline__ void mma_bf16(float (&d)[4], const uint32_t (&a)[4],
                                         uint32_t b0, uint32_t b1) {
    asm volatile(
        "mma.sync.aligned.m16n8k16.row.col.f32.bf16.bf16.f32 "
        "{%0,%1,%2,%3}, {%4,%5,%6,%7}, {%8,%9}, {%0,%1,%2,%3};"
        : "+f"(d[0]), "+f"(d[1]), "+f"(d[2]), "+f"(d[3])
        : "r"(a[0]), "r"(a[1]), "r"(a[2]), "r"(a[3]), "r"(b0), "r"(b1));
}
__device__ __forceinline__ uint32_t bfpack(float lo, float hi) {
    uint32_t d;
    asm("cvt.rn.bf16x2.f32 %0, %1, %2;" : "=r"(d) : "f"(hi), "f"(lo));
    return d;
}
__device__ __forceinline__ float bfhi(float f) {
    return __bfloat162float(__float2bfloat16(f));
}

// ---------------- RoPE tables (double-precision truth) ------------------------
__global__ void rope_table_kernel() {
    int l = blockIdx.x;
    int i = threadIdx.x;                       // 0..63
    double invf = exp(((double)(-2 * i) / 128.0) * log(10000.0));
    double th = (double)l * invf;
    double s, c;
    sincos(th, &s, &c);
    g_cos[l * 64 + i] = (float)c;
    g_sin[l * 64 + i] = (float)s;
}

// ---------------- GEMM core (EXACT R12 — proven) ---------------------------------
#define BM 128
#define BN 128
#define BK 16
#define SAP 132

__device__ __forceinline__ void sgemm_compute_mma(const float* __restrict__ A,
                                                  const float* __restrict__ W,
                                                  int K, int bm, int bn,
                                                  float (&acc)[2][8][4]) {
    __shared__ uint32_t As[2][BK][SAP];
    __shared__ uint32_t Ws[2][BK][SAP];
    const int tid  = threadIdx.x;
    const int warp = tid >> 5, lane = tid & 31;
    const int wm0 = (warp >> 1) * 32, wn0 = (warp & 1) * 64;
    const int lr = lane >> 2;
    const int lc = lane & 3;
    const int ldr = tid >> 2;
    const int ldc = (tid & 3) << 2;

#pragma unroll
    for (int mt = 0; mt < 2; mt++)
#pragma unroll
        for (int nt = 0; nt < 8; nt++)
#pragma unroll
            for (int i = 0; i < 4; i++) acc[mt][nt][i] = 0.f;

    float4 va[2], vw[2];
#pragma unroll
    for (int p = 0; p < 2; p++) {
        int r = ldr + p * 64;
        va[p] = *(const float4*)(A + (size_t)(bm + r) * K + ldc);
        vw[p] = *(const float4*)(W + (size_t)(bn + r) * K + ldc);
    }
#pragma unroll
    for (int p = 0; p < 2; p++) {
        int r = ldr + p * 64;
        As[0][ldc + 0][r] = f2tf32(va[p].x); As[0][ldc + 1][r] = f2tf32(va[p].y);
        As[0][ldc + 2][r] = f2tf32(va[p].z); As[0][ldc + 3][r] = f2tf32(va[p].w);
        Ws[0][ldc + 0][r] = f2tf32(vw[p].x); Ws[0][ldc + 1][r] = f2tf32(vw[p].y);
        Ws[0][ldc + 2][r] = f2tf32(vw[p].z); Ws[0][ldc + 3][r] = f2tf32(vw[p].w);
    }
    __syncthreads();

    const int nit = K / BK;
    for (int it = 0; it < nit; it++) {
        const int cur = it & 1;

        if (it + 1 < nit) {
            const int k0 = (it + 1) * BK;
#pragma unroll
            for (int p = 0; p < 2; p++) {
                int r = ldr + p * 64;
                va[p] = *(const float4*)(A + (size_t)(bm + r) * K + k0 + ldc);
                vw[p] = *(const float4*)(W + (size_t)(bn + r) * K + k0 + ldc);
            }
        }

        const uint32_t (*Ac)[SAP] = As[cur];
        const uint32_t (*Wc)[SAP] = Ws[cur];
#pragma unroll
        for (int ks = 0; ks < BK / 8; ks++) {
            const int kb = ks * 8;
            uint32_t a[2][4];
#pragma unroll
            for (int mt = 0; mt < 2; mt++) {
                const int r = wm0 + mt * 16 + lr;
                a[mt][0] = Ac[kb + lc][r];
                a[mt][1] = Ac[kb + lc][r + 8];
                a[mt][2] = Ac[kb + lc + 4][r];
                a[mt][3] = Ac[kb + lc + 4][r + 8];
            }
#pragma unroll
            for (int nt = 0; nt < 8; nt++) {
                const int n = wn0 + nt * 8 + lr;
                uint32_t b0 = Wc[kb + lc][n];
                uint32_t b1 = Wc[kb + lc + 4][n];
                mma_tf32(acc[0][nt], a[0], b0, b1);
                mma_tf32(acc[1][nt], a[1], b0, b1);
            }
        }

        if (it + 1 < nit) {
            const int nxt = 1 - cur;
#pragma unroll
            for (int p = 0; p < 2; p++) {
                int r = ldr + p * 64;
                As[nxt][ldc + 0][r] = f2tf32(va[p].x);
                As[nxt][ldc + 1][r] = f2tf32(va[p].y);
                As[nxt][ldc + 2][r] = f2tf32(va[p].z);
                As[nxt][ldc + 3][r] = f2tf32(va[p].w);
                Ws[nxt][ldc + 0][r] = f2tf32(vw[p].x);
                Ws[nxt][ldc + 1][r] = f2tf32(vw[p].y);
                Ws[nxt][ldc + 2][r] = f2tf32(vw[p].z);
                Ws[nxt][ldc + 3][r] = f2tf32(vw[p].w);
            }
        }
        __syncthreads();
    }
}

__global__ void __launch_bounds__(256, 2) sgemm_qkv_kernel(const float* __restrict__ x,
                                                           const float* __restrict__ Wq,
                                                           const float* __restrict__ Wk,
                                                           const float* __restrict__ Wv) {
    const int z = blockIdx.z;
    const float* W = (z == 0) ? Wq : (z == 1) ? Wk : Wv;
    float* dst = (z == 0) ? g_q : (z == 1) ? g_k : g_v;
    float acc[2][8][4];
    const int bm = blockIdx.y * BM, bn = blockIdx.x * BN;
    sgemm_compute_mma(x, W, D_, bm, bn, acc);

    const int warp = threadIdx.x >> 5, lane = threadIdx.x & 31;
    const int wm0 = (warp >> 1) * 32, wn0 = (warp & 1) * 64;
    const int lr = lane >> 2, lc = lane & 3;
    const int h = bn >> 7;
#pragma unroll
    for (int mt = 0; mt < 2; mt++) {
        const int mlo = bm + wm0 + mt * 16 + lr;
#pragma unroll
        for (int nt = 0; nt < 8; nt++) {
            const int jj = wn0 + nt * 8 + 2 * lc;
#pragma unroll
            for (int half = 0; half < 2; half++) {
                const int m = mlo + half * 8;
                const int bb = m >> 11, l = m & 2047;
                float* p = dst + (((size_t)(bb * H_ + h) * L_ + l) * HD + jj);
                *(float2*)p = make_float2(acc[mt][nt][half * 2],
                                          acc[mt][nt][half * 2 + 1]);
            }
        }
    }
}

__global__ void __launch_bounds__(256, 2) sgemm_out_kernel(const float* __restrict__ Wo,
                                                           float* __restrict__ C) {
    float acc[2][8][4];
    const int bm = blockIdx.y * BM, bn = blockIdx.x * BN;
    sgemm_compute_mma(g_att, Wo, D_, bm, bn, acc);

    const int warp = threadIdx.x >> 5, lane = threadIdx.x & 31;
    const int wm0 = (warp >> 1) * 32, wn0 = (warp & 1) * 64;
    const int lr = lane >> 2, lc = lane & 3;
#pragma unroll
    for (int mt = 0; mt < 2; mt++) {
        const int mlo = bm + wm0 + mt * 16 + lr;
#pragma unroll
        for (int nt = 0; nt < 8; nt++) {
            const int n0 = bn + wn0 + nt * 8 + 2 * lc;
#pragma unroll
            for (int half = 0; half < 2; half++) {
                const size_t m = mlo + half * 8;
                *(float2*)(C + m * D_ + n0) = make_float2(acc[mt][nt][half * 2],
                                                          acc[mt][nt][half * 2 + 1]);
            }
        }
    }
}

// ---------------- RoPE + sigmoid + row sum-of-squares (restructured) -------------
// One warp per row: lane -> float4 of 4 cols; partner float4 read directly from
// global (cols ^64); warp-reduce sumsq. Grid (BH, L/16), 256 threads = 8 warps,
// 2 row-passes. No block barriers, no smem.
__global__ void __launch_bounds__(256) rope_kernel() {
    const int bh = blockIdx.x;
    const int l0 = blockIdx.y * 16;
    const int warp = threadIdx.x >> 5, lane = threadIdx.x & 31;
    const size_t rowbase = ((size_t)bh * L_ + l0) * HD;

#pragma unroll
    for (int pass = 0; pass < 2; pass++) {
        const int row = warp + pass * 8;         // 0..15
        const int l = l0 + row;
        const size_t base = rowbase + (size_t)row * HD;
        const int c0 = lane * 4;                 // 0..124
        const int pc = (c0 + 64) & 127;          // partner col group
        const float sgn = (c0 < 64) ? -1.f : 1.f;

        float4 cs = *(const float4*)&g_cos[l * 64 + (c0 & 63)];
        float4 sn = *(const float4*)&g_sin[l * 64 + (c0 & 63)];

        // ---- Q ----
        float4 qv = *(const float4*)&g_q[base + c0];
        float4 qp = *(const float4*)&g_q[base + pc];
        float4 qo;
        qo.x = qv.x * cs.x + sgn * qp.x * sn.x;
        qo.y = qv.y * cs.y + sgn * qp.y * sn.y;
        qo.z = qv.z * cs.z + sgn * qp.z * sn.z;
        qo.w = qv.w * cs.w + sgn * qp.w * sn.w;
        float4 qt;
        qt.x = 1.f / (1.f + __expf(-qo.x));
        qt.y = 1.f / (1.f + __expf(-qo.y));
        qt.z = 1.f / (1.f + __expf(-qo.z));
        qt.w = 1.f / (1.f + __expf(-qo.w));

        // ---- K ----
        float4 kv = *(const float4*)&g_k[base + c0];
        float4 kp = *(const float4*)&g_k[base + pc];
        float4 ko;
        ko.x = kv.x * cs.x + sgn * kp.x * sn.x;
        ko.y = kv.y * cs.y + sgn * kp.y * sn.y;
        ko.z = kv.z * cs.z + sgn * kp.z * sn.z;
        ko.w = kv.w * cs.w + sgn * kp.w * sn.w;
        float4 kt;
        kt.x = 1.f / (1.f + __expf(-ko.x));
        kt.y = 1.f / (1.f + __expf(-ko.y));
        kt.z = 1.f / (1.f + __expf(-ko.z));
        kt.w = 1.f / (1.f + __expf(-ko.w));

        __syncwarp();   // all partner reads of this row done before overwrite
        *(float4*)&g_q[base + c0] = qt;
        *(float4*)&g_k[base + c0] = kt;

        float q2 = qt.x * qt.x + qt.y * qt.y + qt.z * qt.z + qt.w * qt.w;
        float k2 = kt.x * kt.x + kt.y * kt.y + kt.z * kt.z + kt.w * kt.w;
#pragma unroll
        for (int o = 16; o; o >>= 1) {
            q2 += __shfl_xor_sync(0xffffffffu, q2, o);
            k2 += __shfl_xor_sync(0xffffffffu, k2, o);
        }
        if (lane == 0) {
            g_qsq[(size_t)bh * L_ + l] = q2;
            g_ksq[(size_t)bh * L_ + l] = k2;
        }
    }
}

// ---------------- causal flash attention (R12 math; heavy-first scheduling) ------
#define QPW 68
#define KPW 68
#define VPW 264
#define FP_STR 68
#define OFF_QH 0
#define OFF_QL (128*QPW)
#define OFF_KH (2*128*QPW)
#define OFF_KL (OFF_KH + 64*KPW)
#define OFF_VP (OFF_KL + 64*KPW)
#define OFF_PS (OFF_VP + 32*VPW)
#define OFF_SQS (OFF_PS + 128*FP_STR)
#define OFF_SKS (OFF_SQS + 128)
#define FLASH_SMEM ((OFF_SKS + 64) * 4)

__global__ void __launch_bounds__(256) flash_kernel(const float* __restrict__ tau_p) {
    extern __shared__ uint32_t smu[];
    float* sqs = (float*)(smu + OFF_SQS);
    float* sks = (float*)(smu + OFF_SKS);
    uint32_t* Pu = smu + OFF_PS;

    const int qi = (L_ / 128 - 1) - blockIdx.x;   // heavy tiles first
    const int bh = blockIdx.y;
    const int b = bh >> 4, h = bh & 15;
    const int tid = threadIdx.x;
    const int lane = tid & 31, warp = tid >> 5;
    const int lr = lane >> 2, lc = lane & 3;
    const int r0 = warp * 16 + lr;

    float tr = tau_p[0];
    float tau = log1pf(expf(tr));
    tau = fminf(fmaxf(tau, 0.1f), 10.f);
    const float inv_tau = 1.f / tau;

    const size_t hbase = (size_t)bh * L_ * HD;
    const float* Qg = g_q + hbase + (size_t)qi * 128 * HD;

#pragma unroll
    for (int t = 0; t < 16; t++) {
        int idx = tid + t * 256;
        int row = idx >> 5, c4 = idx & 31;
        float4 v = *(const float4*)(Qg + (size_t)row * HD + c4 * 4);
        float hx = bfhi(v.x), hy = bfhi(v.y), hz = bfhi(v.z), hw = bfhi(v.w);
        int kpa = 2 * c4, kpb = kpa + 1;
        int sa = kpa >> 3, ja = kpa & 7;
        int ia = row * QPW + ((sa << 2) + (ja & 3)) * 2 + (ja >> 2);
        int sb = kpb >> 3, jb = kpb & 7;
        int ib = row * QPW + ((sb << 2) + (jb & 3)) * 2 + (jb >> 2);
        smu[OFF_QH + ia] = bfpack(hx, hy);
        smu[OFF_QL + ia] = bfpack(v.x - hx, v.y - hy);
        smu[OFF_QH + ib] = bfpack(hz, hw);
        smu[OFF_QL + ib] = bfpack(v.z - hz, v.w - hw);
    }
    if (tid < 128) sqs[tid] = g_qsq[(size_t)bh * L_ + qi * 128 + tid];

    float m_i[2] = {-INFINITY, -INFINITY};
    float l_i[2] = {0.f, 0.f};
    float O[16][4];
#pragma unroll
    for (int nf = 0; nf < 16; nf++)
#pragma unroll
        for (int i = 0; i < 4; i++) O[nf][i] = 0.f;

    const int ntk = 2 * qi + 2;
    for (int kt = 0; kt < ntk; kt++) {
        const int j0 = kt * 64;
        __syncthreads();

#pragma unroll
        for (int t = 0; t < 8; t++) {
            int idx = tid + t * 256;
            int row = idx >> 5, c4 = idx & 31;
            float4 v = *(const float4*)(g_k + hbase + (size_t)(j0 + row) * HD + c4 * 4);
            float hx = bfhi(v.x), hy = bfhi(v.y), hz = bfhi(v.z), hw = bfhi(v.w);
            int kpa = 2 * c4, kpb = kpa + 1;
            int sa = kpa >> 3, ja = kpa & 7;
            int ia = row * KPW + ((sa << 2) + (ja & 3)) * 2 + (ja >> 2);
            int sb = kpb >> 3, jb = kpb & 7;
            int ib = row * KPW + ((sb << 2) + (jb & 3)) * 2 + (jb >> 2);
            smu[OFF_KH + ia] = bfpack(hx, hy);
            smu[OFF_KL + ia] = bfpack(v.x - hx, v.y - hy);
            smu[OFF_KH + ib] = bfpack(hz, hw);
            smu[OFF_KL + ib] = bfpack(v.z - hz, v.w - hw);
        }
#pragma unroll
        for (int t = 0; t < 8; t++) {
            int idx = tid + t * 256;
            int k = idx >> 5, c4 = idx & 31;
            float4 v = *(const float4*)(g_v + hbase + (size_t)(j0 + k) * HD + c4 * 4);
            int ks = k >> 3, j = k & 7;
            int pr = (ks << 2) + (j & 3), half = j >> 2;
            uint32_t base = OFF_VP + pr * VPW + (c4 * 4) * 2 + half;
            smu[base + 0] = f2tf32(v.x);
            smu[base + 2] = f2tf32(v.y);
            smu[base + 4] = f2tf32(v.z);
            smu[base + 6] = f2tf32(v.w);
        }
        if (tid < 64) sks[tid] = g_ksq[(size_t)bh * L_ + j0 + tid];
        __syncthreads();

        float sacc[8][4];
#pragma unroll
        for (int nf = 0; nf < 8; nf++)
#pragma unroll
            for (int i = 0; i < 4; i++) sacc[nf][i] = 0.f;

#pragma unroll
        for (int s8 = 0; s8 < 8; s8++) {
            const int ci = ((s8 << 2) + lc) * 2;
            uint2 qh0 = *(const uint2*)(smu + OFF_QH + r0 * QPW + ci);
            uint2 qh1 = *(const uint2*)(smu + OFF_QH + (r0 + 8) * QPW + ci);
            uint2 ql0 = *(const uint2*)(smu + OFF_QL + r0 * QPW + ci);
            uint2 ql1 = *(const uint2*)(smu + OFF_QL + (r0 + 8) * QPW + ci);
            uint32_t ah[4] = {qh0.x, qh1.x, qh0.y, qh1.y};
            uint32_t al[4] = {ql0.x, ql1.x, ql0.y, ql1.y};
#pragma unroll
            for (int nf = 0; nf < 8; nf++) {
                const int n = nf * 8 + lr;
                uint2 bhp = *(const uint2*)(smu + OFF_KH + n * KPW + ci);
                uint2 blp = *(const uint2*)(smu + OFF_KL + n * KPW + ci);
                mma_bf16(sacc[nf], ah, bhp.x, bhp.y);
                mma_bf16(sacc[nf], ah, blp.x, blp.y);
                mma_bf16(sacc[nf], al, bhp.x, bhp.y);
            }
        }

        const float sq0 = sqs[r0], sq1 = sqs[r0 + 8];
        const int gq0 = qi * 128 + r0, gq1 = gq0 + 8;
        float rm[2] = {-INFINITY, -INFINITY};
#pragma unroll
        for (int nf = 0; nf < 8; nf++) {
            const int cb = j0 + nf * 8 + 2 * lc;
            const float kq0 = sks[nf * 8 + 2 * lc];
            const float kq1 = sks[nf * 8 + 2 * lc + 1];
            float v00 = (2.f * sacc[nf][0] - sq0 - kq0) * inv_tau;
            float v01 = (2.f * sacc[nf][1] - sq0 - kq1) * inv_tau;
            float v10 = (2.f * sacc[nf][2] - sq1 - kq0) * inv_tau;
            float v11 = (2.f * sacc[nf][3] - sq1 - kq1) * inv_tau;
            v00 = (cb > gq0) ? -INFINITY : v00;
            v01 = (cb + 1 > gq0) ? -INFINITY : v01;
            v10 = (cb > gq1) ? -INFINITY : v10;
            v11 = (cb + 1 > gq1) ? -INFINITY : v11;
            sacc[nf][0] = v00; sacc[nf][1] = v01;
            sacc[nf][2] = v10; sacc[nf][3] = v11;
            rm[0] = fmaxf(rm[0], fmaxf(v00, v01));
            rm[1] = fmaxf(rm[1], fmaxf(v10, v11));
        }
#pragma unroll
        for (int i = 0; i < 2; i++) {
            rm[i] = fmaxf(rm[i], __shfl_xor_sync(0xffffffffu, rm[i], 1));
            rm[i] = fmaxf(rm[i], __shfl_xor_sync(0xffffffffu, rm[i], 2));
        }
        float mnew[2], scale[2], rs[2] = {0.f, 0.f};
#pragma unroll
        for (int i = 0; i < 2; i++) {
            mnew[i] = fmaxf(m_i[i], rm[i]);
            scale[i] = __expf(m_i[i] - mnew[i]);
        }
#pragma unroll
        for (int nf = 0; nf < 8; nf++) {
            float p00 = __expf(sacc[nf][0] - mnew[0]);
            float p01 = __expf(sacc[nf][1] - mnew[0]);
            float p10 = __expf(sacc[nf][2] - mnew[1]);
            float p11 = __expf(sacc[nf][3] - mnew[1]);
            rs[0] += p00 + p01;
            rs[1] += p10 + p11;
            const int cc = nf * 8 + 2 * lc;
            *(uint2*)(Pu + r0 * FP_STR + cc) = make_uint2(f2tf32(p00), f2tf32(p01));
            *(uint2*)(Pu + (r0 + 8) * FP_STR + cc) = make_uint2(f2tf32(p10), f2tf32(p11));
        }
#pragma unroll
        for (int i = 0; i < 2; i++) {
            rs[i] += __shfl_xor_sync(0xffffffffu, rs[i], 1);
            rs[i] += __shfl_xor_sync(0xffffffffu, rs[i], 2);
            l_i[i] = l_i[i] * scale[i] + rs[i];
            m_i[i] = mnew[i];
        }
#pragma unroll
        for (int nf = 0; nf < 16; nf++) {
            O[nf][0] *= scale[0]; O[nf][1] *= scale[0];
            O[nf][2] *= scale[1]; O[nf][3] *= scale[1];
        }
        __syncwarp();

#pragma unroll
        for (int ks = 0; ks < 8; ks++) {
            const int kb = ks * 8;
            uint32_t pa[4];
            pa[0] = Pu[r0 * FP_STR + kb + lc];
            pa[1] = Pu[(r0 + 8) * FP_STR + kb + lc];
            pa[2] = Pu[r0 * FP_STR + kb + lc + 4];
            pa[3] = Pu[(r0 + 8) * FP_STR + kb + lc + 4];
            const uint32_t vbase = OFF_VP + ((ks << 2) + lc) * VPW;
#pragma unroll
            for (int nf = 0; nf < 16; nf++) {
                const int n = nf * 8 + lr;
                uint2 bv = *(const uint2*)(smu + vbase + 2 * n);
                mma_tf32(O[nf], pa, bv.x, bv.y);
            }
        }
    }

    const float il0 = 1.f / l_i[0], il1 = 1.f / l_i[1];
    const int gq0 = qi * 128 + r0;
#pragma unroll
    for (int nf = 0; nf < 16; nf++) {
        const int col = nf * 8 + 2 * lc;
        size_t off0 = (((size_t)b * L_ + gq0) * H_ + h) * HD + col;
        size_t off1 = (((size_t)b * L_ + gq0 + 8) * H_ + h) * HD + col;
        *(float2*)&g_att[off0] = make_float2(O[nf][0] * il0, O[nf][1] * il0);
        *(float2*)&g_att[off1] = make_float2(O[nf][2] * il1, O[nf][3] * il1);
    }
}

// ---------------- launch ----------------------------------------------------------
extern "C" void kernel_launch(void* const* d_in, const int* in_sizes, int n_in,
                              void* d_out, int out_size) {
    const float* x   = (const float*)d_in[0];
    const float* Wq  = (const float*)d_in[1];
    const float* Wk  = (const float*)d_in[2];
    const float* Wv  = (const float*)d_in[3];
    const float* Wo  = (const float*)d_in[4];
    const float* tau = (const float*)d_in[5];
    float* out = (float*)d_out;

    cudaFuncSetAttribute(flash_kernel, cudaFuncAttributeMaxDynamicSharedMemorySize,
                         FLASH_SMEM);

    rope_table_kernel<<<L_, 64>>>();
    sgemm_qkv_kernel<<<dim3(D_ / BN, (B_ * L_) / BM, 3), 256>>>(x, Wq, Wk, Wv);
    rope_kernel<<<dim3(BH, L_ / 16), 256>>>();
    flash_kernel<<<dim3(L_ / 128, BH), 256, FLASH_SMEM>>>(tau);
    sgemm_out_kernel<<<dim3(D_ / BN, (B_ * L_) / BM), 256>>>(Wo, out);
}

// round 16
// speedup vs baseline: 1.3064x; 1.0353x over previous
#include <cuda_runtime.h>
#include <cuda_bf16.h>
#include <math.h>
#include <stdint.h>

#define B_  4
#define L_  2048
#define D_  2048
#define H_  16
#define HD  128
#define BH  (B_*H_)

// ---------------- device scratch (allocation-free rule: __device__ globals) ----
__device__ float g_q[(size_t)BH * L_ * HD];     // (B,H,L,d)
__device__ float g_k[(size_t)BH * L_ * HD];     // (B,H,L,d)
__device__ float g_v[(size_t)BH * L_ * HD];     // (B,H,L,d)
__device__ float g_att[(size_t)B_ * L_ * D_];   // (B,L,H,d)
__device__ float g_qsq[BH * L_];
__device__ float g_ksq[BH * L_];
__device__ float g_cos[L_ * 64];
__device__ float g_sin[L_ * 64];

// ---------------- mma helpers ----------------------------------------------------
__device__ __forceinline__ uint32_t f2tf32(float x) {
    uint32_t r;
    asm("cvt.rna.tf32.f32 %0, %1;" : "=r"(r) : "f"(x));
    return r;
}
__device__ __forceinline__ void mma_tf32(float (&d)[4], const uint32_t (&a)[4],
                                         uint32_t b0, uint32_t b1) {
    asm volatile(
        "mma.sync.aligned.m16n8k8.row.col.f32.tf32.tf32.f32 "
        "{%0,%1,%2,%3}, {%4,%5,%6,%7}, {%8,%9}, {%0,%1,%2,%3};"
        : "+f"(d[0]), "+f"(d[1]), "+f"(d[2]), "+f"(d[3])
        : "r"(a[0]), "r"(a[1]), "r"(a[2]), "r"(a[3]), "r"(b0), "r"(b1));
}
__device__ __forceinline__ void mma_bf16(float (&d)[4], const uint32_t (&a)[4],
                                         uint32_t b0, uint32_t b1) {
    asm volatile(
        "mma.sync.aligned.m16n8k16.row.col.f32.bf16.bf16.f32 "
        "{%0,%1,%2,%3}, {%4,%5,%6,%7}, {%8,%9}, {%0,%1,%2,%3};"
        : "+f"(d[0]), "+f"(d[1]), "+f"(d[2]), "+f"(d[3])
        : "r"(a[0]), "r"(a[1]), "r"(a[2]), "r"(a[3]), "r"(b0), "r"(b1));
}
__device__ __forceinline__ uint32_t bfpack(float lo, float hi) {
    uint32_t d;
    asm("cvt.rn.bf16x2.f32 %0, %1, %2;" : "=r"(d) : "f"(hi), "f"(lo));
    return d;
}
__device__ __forceinline__ float bfhi(float f) {
    return __bfloat162float(__float2bfloat16(f));
}

// ---------------- RoPE tables (double-precision truth) ------------------------
__global__ void rope_table_kernel() {
    int l = blockIdx.x;
    int i = threadIdx.x;                       // 0..63
    double invf = exp(((double)(-2 * i) / 128.0) * log(10000.0));
    double th = (double)l * invf;
    double s, c;
    sincos(th, &s, &c);
    g_cos[l * 64 + i] = (float)c;
    g_sin[l * 64 + i] = (float)s;
}

// ---------------- GEMM core: R12 pipeline + paired LDS.64 fragments -------------
// 128x128 CTA tile, 256 threads, 8 warps 4x2, warp tile m32 x n64, BK=16,
// double-buffered with distance-1 register prefetch (R12-proven flow).
// Smem row (per matrix row): 16 tf32 words as 8 (k, k+4) pairs:
//   k -> pos = (k & 8) + (k & 3)*2 + ((k >> 2) & 1),  row stride RSTR=18.
// Fragment loads become LDS.64; stride-8 rows map 9-apart mod 16 (8B banks)
// -> <=2-way conflicts (the R13 RSTR=20 layout was 8-way; that was the bug).
#define BM 128
#define BN 128
#define BK 16
#define RSTR 18

__device__ __forceinline__ void sgemm_compute_mma(const float* __restrict__ A,
                                                  const float* __restrict__ W,
                                                  int K, int bm, int bn,
                                                  float (&acc)[2][8][4]) {
    __shared__ uint32_t As[2][128 * RSTR];
    __shared__ uint32_t Ws[2][128 * RSTR];
    const int tid  = threadIdx.x;
    const int warp = tid >> 5, lane = tid & 31;
    const int wm0 = (warp >> 1) * 32, wn0 = (warp & 1) * 64;
    const int lr = lane >> 2;
    const int lc = lane & 3;
    const int ldr = tid >> 2;              // 0..63
    const int ldc = (tid & 3) << 2;        // 0,4,8,12
    // store base for this thread's 4 consecutive k's (stride-2 slots)
    const int sb0 = (ldc & 8) + ((ldc >> 2) & 1);

#pragma unroll
    for (int mt = 0; mt < 2; mt++)
#pragma unroll
        for (int nt = 0; nt < 8; nt++)
#pragma unroll
            for (int i = 0; i < 4; i++) acc[mt][nt][i] = 0.f;

    float4 va[2], vw[2];
#pragma unroll
    for (int p = 0; p < 2; p++) {
        int r = ldr + p * 64;
        va[p] = *(const float4*)(A + (size_t)(bm + r) * K + ldc);
        vw[p] = *(const float4*)(W + (size_t)(bn + r) * K + ldc);
    }
#pragma unroll
    for (int p = 0; p < 2; p++) {
        int r = ldr + p * 64;
        uint32_t* a = &As[0][r * RSTR + sb0];
        a[0] = f2tf32(va[p].x); a[2] = f2tf32(va[p].y);
        a[4] = f2tf32(va[p].z); a[6] = f2tf32(va[p].w);
        uint32_t* w = &Ws[0][r * RSTR + sb0];
        w[0] = f2tf32(vw[p].x); w[2] = f2tf32(vw[p].y);
        w[4] = f2tf32(vw[p].z); w[6] = f2tf32(vw[p].w);
    }
    __syncthreads();

    const int nit = K / BK;
    for (int it = 0; it < nit; it++) {
        const int cur = it & 1;

        if (it + 1 < nit) {
            const int k0 = (it + 1) * BK;
#pragma unroll
            for (int p = 0; p < 2; p++) {
                int r = ldr + p * 64;
                va[p] = *(const float4*)(A + (size_t)(bm + r) * K + k0 + ldc);
                vw[p] = *(const float4*)(W + (size_t)(bn + r) * K + k0 + ldc);
            }
        }

        const uint32_t* Ab = As[cur];
        const uint32_t* Wb = Ws[cur];
#pragma unroll
        for (int ks = 0; ks < 2; ks++) {
            const int pa = ks * 8 + lc * 2;
            uint32_t a[2][4];
#pragma unroll
            for (int mt = 0; mt < 2; mt++) {
                const int r = wm0 + mt * 16 + lr;
                uint2 u0 = *(const uint2*)(Ab + r * RSTR + pa);
                uint2 u1 = *(const uint2*)(Ab + (r + 8) * RSTR + pa);
                a[mt][0] = u0.x; a[mt][1] = u1.x;
                a[mt][2] = u0.y; a[mt][3] = u1.y;
            }
#pragma unroll
            for (int nt = 0; nt < 8; nt++) {
                const int n = wn0 + nt * 8 + lr;
                uint2 ub = *(const uint2*)(Wb + n * RSTR + pa);
                mma_tf32(acc[0][nt], a[0], ub.x, ub.y);
                mma_tf32(acc[1][nt], a[1], ub.x, ub.y);
            }
        }

        if (it + 1 < nit) {
            const int nxt = 1 - cur;
#pragma unroll
            for (int p = 0; p < 2; p++) {
                int r = ldr + p * 64;
                uint32_t* a = &As[nxt][r * RSTR + sb0];
                a[0] = f2tf32(va[p].x); a[2] = f2tf32(va[p].y);
                a[4] = f2tf32(va[p].z); a[6] = f2tf32(va[p].w);
                uint32_t* w = &Ws[nxt][r * RSTR + sb0];
                w[0] = f2tf32(vw[p].x); w[2] = f2tf32(vw[p].y);
                w[4] = f2tf32(vw[p].z); w[6] = f2tf32(vw[p].w);
            }
        }
        __syncthreads();
    }
}

__global__ void __launch_bounds__(256, 2) sgemm_qkv_kernel(const float* __restrict__ x,
                                                           const float* __restrict__ Wq,
                                                           const float* __restrict__ Wk,
                                                           const float* __restrict__ Wv) {
    const int z = blockIdx.z;
    const float* W = (z == 0) ? Wq : (z == 1) ? Wk : Wv;
    float* dst = (z == 0) ? g_q : (z == 1) ? g_k : g_v;
    float acc[2][8][4];
    const int bm = blockIdx.y * BM, bn = blockIdx.x * BN;
    sgemm_compute_mma(x, W, D_, bm, bn, acc);

    const int warp = threadIdx.x >> 5, lane = threadIdx.x & 31;
    const int wm0 = (warp >> 1) * 32, wn0 = (warp & 1) * 64;
    const int lr = lane >> 2, lc = lane & 3;
    const int h = bn >> 7;
#pragma unroll
    for (int mt = 0; mt < 2; mt++) {
        const int mlo = bm + wm0 + mt * 16 + lr;
#pragma unroll
        for (int nt = 0; nt < 8; nt++) {
            const int jj = wn0 + nt * 8 + 2 * lc;
#pragma unroll
            for (int half = 0; half < 2; half++) {
                const int m = mlo + half * 8;
                const int bb = m >> 11, l = m & 2047;
                float* p = dst + (((size_t)(bb * H_ + h) * L_ + l) * HD + jj);
                *(float2*)p = make_float2(acc[mt][nt][half * 2],
                                          acc[mt][nt][half * 2 + 1]);
            }
        }
    }
}

__global__ void __launch_bounds__(256, 2) sgemm_out_kernel(const float* __restrict__ Wo,
                                                           float* __restrict__ C) {
    float acc[2][8][4];
    const int bm = blockIdx.y * BM, bn = blockIdx.x * BN;
    sgemm_compute_mma(g_att, Wo, D_, bm, bn, acc);

    const int warp = threadIdx.x >> 5, lane = threadIdx.x & 31;
    const int wm0 = (warp >> 1) * 32, wn0 = (warp & 1) * 64;
    const int lr = lane >> 2, lc = lane & 3;
#pragma unroll
    for (int mt = 0; mt < 2; mt++) {
        const int mlo = bm + wm0 + mt * 16 + lr;
#pragma unroll
        for (int nt = 0; nt < 8; nt++) {
            const int n0 = bn + wn0 + nt * 8 + 2 * lc;
#pragma unroll
            for (int half = 0; half < 2; half++) {
                const size_t m = mlo + half * 8;
                *(float2*)(C + m * D_ + n0) = make_float2(acc[mt][nt][half * 2],
                                                          acc[mt][nt][half * 2 + 1]);
            }
        }
    }
}

// ---------------- RoPE + sigmoid + row sum-of-squares (R15 — proven) -------------
__global__ void __launch_bounds__(256) rope_kernel() {
    const int bh = blockIdx.x;
    const int l0 = blockIdx.y * 16;
    const int warp = threadIdx.x >> 5, lane = threadIdx.x & 31;
    const size_t rowbase = ((size_t)bh * L_ + l0) * HD;

#pragma unroll
    for (int pass = 0; pass < 2; pass++) {
        const int row = warp + pass * 8;
        const int l = l0 + row;
        const size_t base = rowbase + (size_t)row * HD;
        const int c0 = lane * 4;
        const int pc = (c0 + 64) & 127;
        const float sgn = (c0 < 64) ? -1.f : 1.f;

        float4 cs = *(const float4*)&g_cos[l * 64 + (c0 & 63)];
        float4 sn = *(const float4*)&g_sin[l * 64 + (c0 & 63)];

        float4 qv = *(const float4*)&g_q[base + c0];
        float4 qp = *(const float4*)&g_q[base + pc];
        float4 qo;
        qo.x = qv.x * cs.x + sgn * qp.x * sn.x;
        qo.y = qv.y * cs.y + sgn * qp.y * sn.y;
        qo.z = qv.z * cs.z + sgn * qp.z * sn.z;
        qo.w = qv.w * cs.w + sgn * qp.w * sn.w;
        float4 qt;
        qt.x = 1.f / (1.f + __expf(-qo.x));
        qt.y = 1.f / (1.f + __expf(-qo.y));
        qt.z = 1.f / (1.f + __expf(-qo.z));
        qt.w = 1.f / (1.f + __expf(-qo.w));

        float4 kv = *(const float4*)&g_k[base + c0];
        float4 kp = *(const float4*)&g_k[base + pc];
        float4 ko;
        ko.x = kv.x * cs.x + sgn * kp.x * sn.x;
        ko.y = kv.y * cs.y + sgn * kp.y * sn.y;
        ko.z = kv.z * cs.z + sgn * kp.z * sn.z;
        ko.w = kv.w * cs.w + sgn * kp.w * sn.w;
        float4 kt;
        kt.x = 1.f / (1.f + __expf(-ko.x));
        kt.y = 1.f / (1.f + __expf(-ko.y));
        kt.z = 1.f / (1.f + __expf(-ko.z));
        kt.w = 1.f / (1.f + __expf(-ko.w));

        __syncwarp();
        *(float4*)&g_q[base + c0] = qt;
        *(float4*)&g_k[base + c0] = kt;

        float q2 = qt.x * qt.x + qt.y * qt.y + qt.z * qt.z + qt.w * qt.w;
        float k2 = kt.x * kt.x + kt.y * kt.y + kt.z * kt.z + kt.w * kt.w;
#pragma unroll
        for (int o = 16; o; o >>= 1) {
            q2 += __shfl_xor_sync(0xffffffffu, q2, o);
            k2 += __shfl_xor_sync(0xffffffffu, k2, o);
        }
        if (lane == 0) {
            g_qsq[(size_t)bh * L_ + l] = q2;
            g_ksq[(size_t)bh * L_ + l] = k2;
        }
    }
}

// ---------------- causal flash attention (R15 — proven) --------------------------
#define QPW 68
#define KPW 68
#define VPW 264
#define FP_STR 68
#define OFF_QH 0
#define OFF_QL (128*QPW)
#define OFF_KH (2*128*QPW)
#define OFF_KL (OFF_KH + 64*KPW)
#define OFF_VP (OFF_KL + 64*KPW)
#define OFF_PS (OFF_VP + 32*VPW)
#define OFF_SQS (OFF_PS + 128*FP_STR)
#define OFF_SKS (OFF_SQS + 128)
#define FLASH_SMEM ((OFF_SKS + 64) * 4)

__global__ void __launch_bounds__(256) flash_kernel(const float* __restrict__ tau_p) {
    extern __shared__ uint32_t smu[];
    float* sqs = (float*)(smu + OFF_SQS);
    float* sks = (float*)(smu + OFF_SKS);
    uint32_t* Pu = smu + OFF_PS;

    const int qi = (L_ / 128 - 1) - blockIdx.x;   // heavy tiles first
    const int bh = blockIdx.y;
    const int b = bh >> 4, h = bh & 15;
    const int tid = threadIdx.x;
    const int lane = tid & 31, warp = tid >> 5;
    const int lr = lane >> 2, lc = lane & 3;
    const int r0 = warp * 16 + lr;

    float tr = tau_p[0];
    float tau = log1pf(expf(tr));
    tau = fminf(fmaxf(tau, 0.1f), 10.f);
    const float inv_tau = 1.f / tau;

    const size_t hbase = (size_t)bh * L_ * HD;
    const float* Qg = g_q + hbase + (size_t)qi * 128 * HD;

#pragma unroll
    for (int t = 0; t < 16; t++) {
        int idx = tid + t * 256;
        int row = idx >> 5, c4 = idx & 31;
        float4 v = *(const float4*)(Qg + (size_t)row * HD + c4 * 4);
        float hx = bfhi(v.x), hy = bfhi(v.y), hz = bfhi(v.z), hw = bfhi(v.w);
        int kpa = 2 * c4, kpb = kpa + 1;
        int sa = kpa >> 3, ja = kpa & 7;
        int ia = row * QPW + ((sa << 2) + (ja & 3)) * 2 + (ja >> 2);
        int sb = kpb >> 3, jb = kpb & 7;
        int ib = row * QPW + ((sb << 2) + (jb & 3)) * 2 + (jb >> 2);
        smu[OFF_QH + ia] = bfpack(hx, hy);
        smu[OFF_QL + ia] = bfpack(v.x - hx, v.y - hy);
        smu[OFF_QH + ib] = bfpack(hz, hw);
        smu[OFF_QL + ib] = bfpack(v.z - hz, v.w - hw);
    }
    if (tid < 128) sqs[tid] = g_qsq[(size_t)bh * L_ + qi * 128 + tid];

    float m_i[2] = {-INFINITY, -INFINITY};
    float l_i[2] = {0.f, 0.f};
    float O[16][4];
#pragma unroll
    for (int nf = 0; nf < 16; nf++)
#pragma unroll
        for (int i = 0; i < 4; i++) O[nf][i] = 0.f;

    const int ntk = 2 * qi + 2;
    for (int kt = 0; kt < ntk; kt++) {
        const int j0 = kt * 64;
        __syncthreads();

#pragma unroll
        for (int t = 0; t < 8; t++) {
            int idx = tid + t * 256;
            int row = idx >> 5, c4 = idx & 31;
            float4 v = *(const float4*)(g_k + hbase + (size_t)(j0 + row) * HD + c4 * 4);
            float hx = bfhi(v.x), hy = bfhi(v.y), hz = bfhi(v.z), hw = bfhi(v.w);
            int kpa = 2 * c4, kpb = kpa + 1;
            int sa = kpa >> 3, ja = kpa & 7;
            int ia = row * KPW + ((sa << 2) + (ja & 3)) * 2 + (ja >> 2);
            int sb = kpb >> 3, jb = kpb & 7;
            int ib = row * KPW + ((sb << 2) + (jb & 3)) * 2 + (jb >> 2);
            smu[OFF_KH + ia] = bfpack(hx, hy);
            smu[OFF_KL + ia] = bfpack(v.x - hx, v.y - hy);
            smu[OFF_KH + ib] = bfpack(hz, hw);
            smu[OFF_KL + ib] = bfpack(v.z - hz, v.w - hw);
        }
#pragma unroll
        for (int t = 0; t < 8; t++) {
            int idx = tid + t * 256;
            int k = idx >> 5, c4 = idx & 31;
            float4 v = *(const float4*)(g_v + hbase + (size_t)(j0 + k) * HD + c4 * 4);
            int ks = k >> 3, j = k & 7;
            int pr = (ks << 2) + (j & 3), half = j >> 2;
            uint32_t base = OFF_VP + pr * VPW + (c4 * 4) * 2 + half;
            smu[base + 0] = f2tf32(v.x);
            smu[base + 2] = f2tf32(v.y);
            smu[base + 4] = f2tf32(v.z);
            smu[base + 6] = f2tf32(v.w);
        }
        if (tid < 64) sks[tid] = g_ksq[(size_t)bh * L_ + j0 + tid];
        __syncthreads();

        float sacc[8][4];
#pragma unroll
        for (int nf = 0; nf < 8; nf++)
#pragma unroll
            for (int i = 0; i < 4; i++) sacc[nf][i] = 0.f;

#pragma unroll
        for (int s8 = 0; s8 < 8; s8++) {
            const int ci = ((s8 << 2) + lc) * 2;
            uint2 qh0 = *(const uint2*)(smu + OFF_QH + r0 * QPW + ci);
            uint2 qh1 = *(const uint2*)(smu + OFF_QH + (r0 + 8) * QPW + ci);
            uint2 ql0 = *(const uint2*)(smu + OFF_QL + r0 * QPW + ci);
            uint2 ql1 = *(const uint2*)(smu + OFF_QL + (r0 + 8) * QPW + ci);
            uint32_t ah[4] = {qh0.x, qh1.x, qh0.y, qh1.y};
            uint32_t al[4] = {ql0.x, ql1.x, ql0.y, ql1.y};
#pragma unroll
            for (int nf = 0; nf < 8; nf++) {
                const int n = nf * 8 + lr;
                uint2 bhp = *(const uint2*)(smu + OFF_KH + n * KPW + ci);
                uint2 blp = *(const uint2*)(smu + OFF_KL + n * KPW + ci);
                mma_bf16(sacc[nf], ah, bhp.x, bhp.y);
                mma_bf16(sacc[nf], ah, blp.x, blp.y);
                mma_bf16(sacc[nf], al, bhp.x, bhp.y);
            }
        }

        const float sq0 = sqs[r0], sq1 = sqs[r0 + 8];
        const int gq0 = qi * 128 + r0, gq1 = gq0 + 8;
        float rm[2] = {-INFINITY, -INFINITY};
#pragma unroll
        for (int nf = 0; nf < 8; nf++) {
            const int cb = j0 + nf * 8 + 2 * lc;
            const float kq0 = sks[nf * 8 + 2 * lc];
            const float kq1 = sks[nf * 8 + 2 * lc + 1];
            float v00 = (2.f * sacc[nf][0] - sq0 - kq0) * inv_tau;
            float v01 = (2.f * sacc[nf][1] - sq0 - kq1) * inv_tau;
            float v10 = (2.f * sacc[nf][2] - sq1 - kq0) * inv_tau;
            float v11 = (2.f * sacc[nf][3] - sq1 - kq1) * inv_tau;
            v00 = (cb > gq0) ? -INFINITY : v00;
            v01 = (cb + 1 > gq0) ? -INFINITY : v01;
            v10 = (cb > gq1) ? -INFINITY : v10;
            v11 = (cb + 1 > gq1) ? -INFINITY : v11;
            sacc[nf][0] = v00; sacc[nf][1] = v01;
            sacc[nf][2] = v10; sacc[nf][3] = v11;
            rm[0] = fmaxf(rm[0], fmaxf(v00, v01));
            rm[1] = fmaxf(rm[1], fmaxf(v10, v11));
        }
#pragma unroll
        for (int i = 0; i < 2; i++) {
            rm[i] = fmaxf(rm[i], __shfl_xor_sync(0xffffffffu, rm[i], 1));
            rm[i] = fmaxf(rm[i], __shfl_xor_sync(0xffffffffu, rm[i], 2));
        }
        float mnew[2], scale[2], rs[2] = {0.f, 0.f};
#pragma unroll
        for (int i = 0; i < 2; i++) {
            mnew[i] = fmaxf(m_i[i], rm[i]);
            scale[i] = __expf(m_i[i] - mnew[i]);
        }
#pragma unroll
        for (int nf = 0; nf < 8; nf++) {
            float p00 = __expf(sacc[nf][0] - mnew[0]);
            float p01 = __expf(sacc[nf][1] - mnew[0]);
            float p10 = __expf(sacc[nf][2] - mnew[1]);
            float p11 = __expf(sacc[nf][3] - mnew[1]);
            rs[0] += p00 + p01;
            rs[1] += p10 + p11;
            const int cc = nf * 8 + 2 * lc;
            *(uint2*)(Pu + r0 * FP_STR + cc) = make_uint2(f2tf32(p00), f2tf32(p01));
            *(uint2*)(Pu + (r0 + 8) * FP_STR + cc) = make_uint2(f2tf32(p10), f2tf32(p11));
        }
#pragma unroll
        for (int i = 0; i < 2; i++) {
            rs[i] += __shfl_xor_sync(0xffffffffu, rs[i], 1);
            rs[i] += __shfl_xor_sync(0xffffffffu, rs[i], 2);
            l_i[i] = l_i[i] * scale[i] + rs[i];
            m_i[i] = mnew[i];
        }
#pragma unroll
        for (int nf = 0; nf < 16; nf++) {
            O[nf][0] *= scale[0]; O[nf][1] *= scale[0];
            O[nf][2] *= scale[1]; O[nf][3] *= scale[1];
        }
        __syncwarp();

#pragma unroll
        for (int ks = 0; ks < 8; ks++) {
            const int kb = ks * 8;
            uint32_t pa[4];
            pa[0] = Pu[r0 * FP_STR + kb + lc];
            pa[1] = Pu[(r0 + 8) * FP_STR + kb + lc];
            pa[2] = Pu[r0 * FP_STR + kb + lc + 4];
            pa[3] = Pu[(r0 + 8) * FP_STR + kb + lc + 4];
            const uint32_t vbase = OFF_VP + ((ks << 2) + lc) * VPW;
#pragma unroll
            for (int nf = 0; nf < 16; nf++) {
                const int n = nf * 8 + lr;
                uint2 bv = *(const uint2*)(smu + vbase + 2 * n);
                mma_tf32(O[nf], pa, bv.x, bv.y);
            }
        }
    }

    const float il0 = 1.f / l_i[0], il1 = 1.f / l_i[1];
    const int gq0 = qi * 128 + r0;
#pragma unroll
    for (int nf = 0; nf < 16; nf++) {
        const int col = nf * 8 + 2 * lc;
        size_t off0 = (((size_t)b * L_ + gq0) * H_ + h) * HD + col;
        size_t off1 = (((size_t)b * L_ + gq0 + 8) * H_ + h) * HD + col;
        *(float2*)&g_att[off0] = make_float2(O[nf][0] * il0, O[nf][1] * il0);
        *(float2*)&g_att[off1] = make_float2(O[nf][2] * il1, O[nf][3] * il1);
    }
}

// ---------------- launch ----------------------------------------------------------
extern "C" void kernel_launch(void* const* d_in, const int* in_sizes, int n_in,
                              void* d_out, int out_size) {
    const float* x   = (const float*)d_in[0];
    const float* Wq  = (const float*)d_in[1];
    const float* Wk  = (const float*)d_in[2];
    const float* Wv  = (const float*)d_in[3];
    const float* Wo  = (const float*)d_in[4];
    const float* tau = (const float*)d_in[5];
    float* out = (float*)d_out;

    cudaFuncSetAttribute(flash_kernel, cudaFuncAttributeMaxDynamicSharedMemorySize,
                         FLASH_SMEM);

    rope_table_kernel<<<L_, 64>>>();
    sgemm_qkv_kernel<<<dim3(D_ / BN, (B_ * L_) / BM, 3), 256>>>(x, Wq, Wk, Wv);
    rope_kernel<<<dim3(BH, L_ / 16), 256>>>();
    flash_kernel<<<dim3(L_ / 128, BH), 256, FLASH_SMEM>>>(tau);
    sgemm_out_kernel<<<dim3(D_ / BN, (B_ * L_) / BM), 256>>>(Wo, out);
}